// round 12
// baseline (speedup 1.0000x reference)
#include <cuda_runtime.h>
#include <cuda_bf16.h>

// WeaveLayer permutation:
//   out[b, yb*8 + hi*4 + px, xb*8 + wi*4 + py] = in[b, yb*4 + py, xb*4 + px, q=2*hi+wi]
// in (32, 768, 768, 4) f32, out (32, 1536, 1536, 1) f32.
//
// R10: persistent CTAs + atomic work-stealing ticket + software pipeline.
//  - Tile = (b, yb): 4 input rows (48 KB contiguous read) -> 8 output rows
//    (48 KB contiguous write). smem tile in OUTPUT layout with the verified
//    conflict-free XOR swizzle from R5: physical_c4 = c4 ^ f(px), f = px+((px&2)<<1).
//  - Pipeline: while LDS+STG of tile t runs, LDGs of tile t+1 are in flight.
//  - Work-stealing (CHUNK=4 consecutive tiles per ticket) removes the ~6%
//    last-wave drain and makes the kernel robust to the achieved occupancy.
//  - Ticket counter reset by an init kernel each launch (deterministic, graphable).

#define TILES   6144          // 32 b * 192 yb
#define GRID    592
#define THREADS 512
#define CHUNK   4             // TILES % CHUNK == 0
#define ROWLEN  1536

__device__ unsigned int g_ticket;

__global__ void weave_init() { g_ticket = 0u; }

__global__ __launch_bounds__(THREADS, 3) void weave_kernel(
    const float4* __restrict__ in4,   // (32, 768, 768) pixels, 1 float4 each
    float4* __restrict__ out4)        // (32, 1536, 384) float4
{
    __shared__ float smem[8 * ROWLEN];      // 48 KB
    __shared__ unsigned int s_base;

    const int tid = threadIdx.x;
    // Load-phase lane map (invariant across the 6 sub-iterations, since k*512
    // only changes bits >= 9): py = tid&3, px = bits 2-3, xb0 = tid>>4 (0..31).
    const int py  = tid & 3;
    const int px  = (tid >> 2) & 3;
    const int xb0 = tid >> 4;
    const int f   = px + ((px & 2) << 1);          // {0,1,6,7}
    // gmem load offset for k=0; k adds 128 (xb += 32 -> xl += 128)
    const int ldoff = py * 768 + (xb0 << 2) + px;
    // smem STS addresses for k=0; k adds 256 (xb<<1 += 64, XOR leaves low bits)
    const int a00_0 = px * ROWLEN + ((((xb0 << 1)    ) ^ f) << 2) + py;
    const int a01_0 = px * ROWLEN + ((((xb0 << 1) | 1) ^ f) << 2) + py;

    float4 v0, v1, v2, v3, v4, v5;

    while (true) {
        if (tid == 0) s_base = atomicAdd(&g_ticket, CHUNK);
        __syncthreads();
        const unsigned int base = s_base;
        if (base >= TILES) break;

        // ---- prologue: issue loads for first tile of chunk ----
        int tile = (int)base;
        int b  = tile / 192;
        int yb = tile - b * 192;
        int in_base = (b * 768 + yb * 4) * 768;
        v0 = in4[in_base + ldoff      ];
        v1 = in4[in_base + ldoff + 128];
        v2 = in4[in_base + ldoff + 256];
        v3 = in4[in_base + ldoff + 384];
        v4 = in4[in_base + ldoff + 512];
        v5 = in4[in_base + ldoff + 640];

        #pragma unroll
        for (int c = 0; c < CHUNK; c++) {
            // ---- STS current tile (regs -> smem, conflict-free) ----
            #pragma unroll
            for (int k = 0; k < 6; k++) {
                const float4 v = (k == 0) ? v0 : (k == 1) ? v1 : (k == 2) ? v2
                               : (k == 3) ? v3 : (k == 4) ? v4 : v5;
                const int a00 = a00_0 + 256 * k;
                const int a01 = a01_0 + 256 * k;
                smem[a00]              = v.x;   // q=0: hi=0, wi=0
                smem[a01]              = v.y;   // q=1: hi=0, wi=1
                smem[a00 + 4 * ROWLEN] = v.z;   // q=2: hi=1, wi=0
                smem[a01 + 4 * ROWLEN] = v.w;   // q=3: hi=1, wi=1
            }
            __syncthreads();

            // ---- prefetch next tile of this chunk into regs (overlaps STG) ----
            int nb = b, nyb = yb;
            if (c + 1 < CHUNK) {
                const int nt = tile + 1;               // base%CHUNK==0, TILES%CHUNK==0
                nb  = nt / 192;
                nyb = nt - nb * 192;
                const int nib = (nb * 768 + nyb * 4) * 768;
                v0 = in4[nib + ldoff      ];
                v1 = in4[nib + ldoff + 128];
                v2 = in4[nib + ldoff + 256];
                v3 = in4[nib + ldoff + 384];
                v4 = in4[nib + ldoff + 512];
                v5 = in4[nib + ldoff + 640];
            }

            // ---- store phase: 8 rows x 384 float4, fully coalesced ----
            const int out_base = (b * 1536 + yb * 8) * 384;
            #pragma unroll
            for (int k = 0; k < 6; k++) {
                const int j  = tid + k * THREADS;      // 0..3071
                const int r  = j / 384;                // 0..7
                const int c4 = j - r * 384;            // 0..383
                const int rp = r & 3;
                const int fs = rp + ((rp & 2) << 1);
                const float4 w = *reinterpret_cast<const float4*>(
                    &smem[r * ROWLEN + ((c4 ^ fs) << 2)]);
                out4[out_base + r * 384 + c4] = w;
            }
            __syncthreads();   // smem reuse guard for next STS / s_base rewrite

            tile = tile + 1;
            b = nb; yb = nyb;
        }
    }
}

extern "C" void kernel_launch(void* const* d_in, const int* in_sizes, int n_in,
                              void* d_out, int out_size) {
    const float4* in4 = (const float4*)d_in[0];
    float4* out4 = (float4*)d_out;
    weave_init<<<1, 1>>>();
    weave_kernel<<<GRID, THREADS>>>(in4, out4);
}